// round 2
// baseline (speedup 1.0000x reference)
#include <cuda_runtime.h>

#define NN 4096
#define BB 8
#define NBTOT (BB*NN)

// ------------- scratch: one big device global (no allocations) -------------
#define BUF 2097152  // BB*64*NN
__device__ float SCR[8*BUF + 2*BB*NN + 256 + 5*128];

// stats slot layout: stat[c] = sum, stat[64+c] = sumsq
__device__ __forceinline__ void bn_coef(const float* __restrict__ stat,
                                        const float* __restrict__ g,
                                        const float* __restrict__ be,
                                        int c, float& sc, float& sh) {
    const float inv = 1.0f / (float)NBTOT;
    float mean = stat[c] * inv;
    float var  = stat[64 + c] * inv - mean * mean;
    float r = rsqrtf(var + 1e-5f);
    sc = g[c] * r;
    sh = be[c] - sc * mean;
}

// per-channel sum & sumsq over (B,N); grid = C, 256 thr; deterministic order
__global__ void k_stats(const float* __restrict__ d, int C, float* __restrict__ stat) {
    int c = blockIdx.x;
    float s = 0.f, sq = 0.f;
    for (int i = threadIdx.x; i < NBTOT; i += 256) {
        int b = i >> 12, n = i & 4095;
        float v = d[(b * C + c) * NN + n];
        s += v; sq += v * v;
    }
    __shared__ float shs[8], shq[8];
    for (int o = 16; o; o >>= 1) {
        s  += __shfl_down_sync(0xffffffffu, s, o);
        sq += __shfl_down_sync(0xffffffffu, sq, o);
    }
    if ((threadIdx.x & 31) == 0) { shs[threadIdx.x >> 5] = s; shq[threadIdx.x >> 5] = sq; }
    __syncthreads();
    if (threadIdx.x == 0) {
        float S = 0.f, Q = 0.f;
        #pragma unroll
        for (int i = 0; i < 8; i++) { S += shs[i]; Q += shq[i]; }
        stat[c] = S; stat[64 + c] = Q;
    }
}

// stem conv: x[8,6,N] -> y[8,32,N]
__global__ void k_conv1(const float* __restrict__ x, const float* __restrict__ w,
                        const float* __restrict__ bias, float* __restrict__ y) {
    __shared__ float ws[192], bs[32];
    int t = threadIdx.x;
    if (t < 192) ws[t] = w[t];
    if (t < 32)  bs[t] = bias[t];
    __syncthreads();
    int b = blockIdx.y, n = blockIdx.x * 256 + t;
    float in[6];
    #pragma unroll
    for (int c = 0; c < 6; c++) in[c] = x[(b * 6 + c) * NN + n];
    #pragma unroll
    for (int o = 0; o < 32; o++) {
        float a = bs[o];
        #pragma unroll
        for (int c = 0; c < 6; c++) a = fmaf(ws[o * 6 + c], in[c], a);
        y[(b * 32 + o) * NN + n] = a;
    }
}

// BN(stats)+relu then 32x32 conv
__global__ void k_bnconv32(const float* __restrict__ yin, const float* __restrict__ stat,
                           const float* __restrict__ g, const float* __restrict__ be,
                           const float* __restrict__ w, const float* __restrict__ bias,
                           float* __restrict__ yout) {
    __shared__ float ws[1024], bs[32], sc[32], sh[32];
    int t = threadIdx.x;
    for (int i = t; i < 1024; i += 256) ws[i] = w[i];
    if (t < 32) { bs[t] = bias[t]; bn_coef(stat, g, be, t, sc[t], sh[t]); }
    __syncthreads();
    int b = blockIdx.y, n = blockIdx.x * 256 + t;
    float in[32];
    #pragma unroll
    for (int c = 0; c < 32; c++)
        in[c] = fmaxf(fmaf(sc[c], yin[(b * 32 + c) * NN + n], sh[c]), 0.f);
    for (int o = 0; o < 32; o++) {
        float a = bs[o];
        #pragma unroll
        for (int c = 0; c < 32; c++) a = fmaf(ws[o * 32 + c], in[c], a);
        yout[(b * 32 + o) * NN + n] = a;
    }
}

// BN+relu -> h; qk = wqk@h; v = wv@h + bv
template<int C>
__global__ void k_bnqkv(const float* __restrict__ yin, const float* __restrict__ stat,
                        const float* __restrict__ g, const float* __restrict__ be,
                        const float* __restrict__ wqk, const float* __restrict__ wv,
                        const float* __restrict__ bv,
                        float* __restrict__ h, float* __restrict__ qk, float* __restrict__ v) {
    __shared__ float wq_s[C*C], wv_s[C*C], bvs[C], sc[C], sh[C];
    int t = threadIdx.x;
    for (int i = t; i < C*C; i += 256) { wq_s[i] = wqk[i]; wv_s[i] = wv[i]; }
    if (t < C) { bvs[t] = bv[t]; bn_coef(stat, g, be, t, sc[t], sh[t]); }
    __syncthreads();
    int b = blockIdx.y, n = blockIdx.x * 256 + t;
    float in[C];
    #pragma unroll
    for (int c = 0; c < C; c++) {
        float val = fmaxf(fmaf(sc[c], yin[(b * C + c) * NN + n], sh[c]), 0.f);
        in[c] = val;
        h[(b * C + c) * NN + n] = val;
    }
    for (int o = 0; o < C; o++) {
        float aq = 0.f, av = bvs[o];
        #pragma unroll
        for (int c = 0; c < C; c++) {
            aq = fmaf(wq_s[o * C + c], in[c], aq);
            av = fmaf(wv_s[o * C + c], in[c], av);
        }
        qk[(b * C + o) * NN + n] = aq;
        v [(b * C + o) * NN + n] = av;
    }
}

// ---------------- attention pass A: per-row max + sumexp ----------------
// grid (NN/128, BB), 256 thr. Each thread: 8x8 microtile of the 128x128 S tile.
template<int C>
__global__ void k_attA(const float* __restrict__ qk, float* __restrict__ Mr,
                       float* __restrict__ iL) {
    __shared__ union U {
        struct { float A[32][128]; float B[32][128]; } t;
        struct { float M[128][17]; float L[128][17]; } r;
    } sm;
    const int b = blockIdx.y, n0 = blockIdx.x * 128, t = threadIdx.x;
    const int rowg = t >> 4, colg = t & 15;
    float Mloc[8], Lloc[8];
    #pragma unroll
    for (int i = 0; i < 8; i++) { Mloc[i] = -1e30f; Lloc[i] = 0.f; }

    for (int mt = 0; mt < NN / 128; mt++) {
        const int m0 = mt * 128;
        float acc[8][8];
        #pragma unroll
        for (int i = 0; i < 8; i++)
            #pragma unroll
            for (int j = 0; j < 8; j++) acc[i][j] = 0.f;
        for (int ck = 0; ck < C / 32; ck++) {
            __syncthreads();
            for (int idx = t; idx < 4096; idx += 256) {
                int k = idx >> 7, i = idx & 127;
                sm.t.A[k][i] = qk[(b * C + ck * 32 + k) * NN + n0 + i];
                sm.t.B[k][i] = qk[(b * C + ck * 32 + k) * NN + m0 + i];
            }
            __syncthreads();
            #pragma unroll
            for (int k = 0; k < 32; k++) {
                float4 a0 = *(float4*)&sm.t.A[k][rowg * 8];
                float4 a1 = *(float4*)&sm.t.A[k][rowg * 8 + 4];
                float4 b0 = *(float4*)&sm.t.B[k][colg * 8];
                float4 b1 = *(float4*)&sm.t.B[k][colg * 8 + 4];
                float a[8] = {a0.x,a0.y,a0.z,a0.w,a1.x,a1.y,a1.z,a1.w};
                float bb[8] = {b0.x,b0.y,b0.z,b0.w,b1.x,b1.y,b1.z,b1.w};
                #pragma unroll
                for (int i = 0; i < 8; i++)
                    #pragma unroll
                    for (int j = 0; j < 8; j++) acc[i][j] = fmaf(a[i], bb[j], acc[i][j]);
            }
        }
        // online softmax update (per-thread column subset)
        #pragma unroll
        for (int i = 0; i < 8; i++) {
            float tmax = acc[i][0];
            #pragma unroll
            for (int j = 1; j < 8; j++) tmax = fmaxf(tmax, acc[i][j]);
            float Mn = fmaxf(Mloc[i], tmax);
            float l = Lloc[i] * __expf(Mloc[i] - Mn);
            #pragma unroll
            for (int j = 0; j < 8; j++) l += __expf(acc[i][j] - Mn);
            Mloc[i] = Mn; Lloc[i] = l;
        }
    }
    __syncthreads();
    #pragma unroll
    for (int i = 0; i < 8; i++) {
        sm.r.M[rowg * 8 + i][colg] = Mloc[i];
        sm.r.L[rowg * 8 + i][colg] = Lloc[i];
    }
    __syncthreads();
    if (t < 128) {
        float M = -1e30f, L = 0.f;
        #pragma unroll
        for (int p = 0; p < 16; p++) {
            float m2 = sm.r.M[t][p], l2 = sm.r.L[t][p];
            float Mn = fmaxf(M, m2);
            L = L * __expf(M - Mn) + l2 * __expf(m2 - Mn);
            M = Mn;
        }
        Mr[b * NN + n0 + t] = M;
        iL[b * NN + n0 + t] = 1.0f / L;
    }
}

// ---------------- attention pass B: column sums + V*attn + renorm ----------------
// grid (NN/128 col-tiles, BB), 256 thr, dynamic smem
template<int C>
__global__ void k_attB(const float* __restrict__ qk, const float* __restrict__ v,
                       const float* __restrict__ Mr, const float* __restrict__ iLp,
                       float* __restrict__ xr) {
    extern __shared__ float dsm[];
    float* Qm   = dsm;               // C*128
    float* Qn   = Qm + C * 128;      // C*32
    float* Vs   = Qn + C * 32;       // C*32
    float* Es   = Vs + C * 32;       // 32*132
    float* sred = Es + 32 * 132;     // 256
    float* sinv = sred + 256;        // 128
    __shared__ float Ms[32], Ls[32];

    const int b = blockIdx.y, m0 = blockIdx.x * 128, t = threadIdx.x;
    for (int idx = t; idx < C * 128; idx += 256) {
        int k = idx >> 7, j = idx & 127;
        Qm[k * 128 + j] = qk[(b * C + k) * NN + m0 + j];
    }
    const int i0 = (t >> 5) * 4;       // S rows (0..28)
    const int j0 = (t & 31) * 4;       // S / u cols (0..124)
    const int c0 = (t >> 5) * (C / 8); // u channels
    const int jjs = t & 127, hf = t >> 7;
    float u[C / 8][4];
    #pragma unroll
    for (int ci = 0; ci < C / 8; ci++)
        #pragma unroll
        for (int jj = 0; jj < 4; jj++) u[ci][jj] = 0.f;
    float sacc = 0.f;

    for (int nt = 0; nt < NN / 32; nt++) {
        const int n0 = nt * 32;
        __syncthreads();
        for (int idx = t; idx < C * 32; idx += 256) {
            int k = idx >> 5, i = idx & 31;
            Qn[k * 32 + i] = qk[(b * C + k) * NN + n0 + i];
            Vs[k * 32 + i] = v [(b * C + k) * NN + n0 + i];
        }
        if (t < 32) { Ms[t] = Mr[b * NN + n0 + t]; Ls[t] = iLp[b * NN + n0 + t]; }
        __syncthreads();
        float s4[4][4];
        #pragma unroll
        for (int i = 0; i < 4; i++)
            #pragma unroll
            for (int j = 0; j < 4; j++) s4[i][j] = 0.f;
        #pragma unroll
        for (int k = 0; k < C; k++) {
            float4 av = *(float4*)&Qn[k * 32 + i0];
            float4 bv4 = *(float4*)&Qm[k * 128 + j0];
            float a[4] = {av.x, av.y, av.z, av.w};
            float bb[4] = {bv4.x, bv4.y, bv4.z, bv4.w};
            #pragma unroll
            for (int i = 0; i < 4; i++)
                #pragma unroll
                for (int j = 0; j < 4; j++) s4[i][j] = fmaf(a[i], bb[j], s4[i][j]);
        }
        #pragma unroll
        for (int ii = 0; ii < 4; ii++) {
            float m = Ms[i0 + ii], il = Ls[i0 + ii];
            float4 ev;
            ev.x = __expf(s4[ii][0] - m) * il;
            ev.y = __expf(s4[ii][1] - m) * il;
            ev.z = __expf(s4[ii][2] - m) * il;
            ev.w = __expf(s4[ii][3] - m) * il;
            *(float4*)&Es[(i0 + ii) * 132 + j0] = ev;
        }
        __syncthreads();
        #pragma unroll
        for (int i = 0; i < 16; i++) sacc += Es[(hf * 16 + i) * 132 + jjs];
        #pragma unroll
        for (int i = 0; i < 32; i++) {
            float4 ev = *(float4*)&Es[i * 132 + j0];
            #pragma unroll
            for (int ci = 0; ci < C / 8; ci++) {
                float a = Vs[(c0 + ci) * 32 + i];
                u[ci][0] = fmaf(a, ev.x, u[ci][0]);
                u[ci][1] = fmaf(a, ev.y, u[ci][1]);
                u[ci][2] = fmaf(a, ev.z, u[ci][2]);
                u[ci][3] = fmaf(a, ev.w, u[ci][3]);
            }
        }
    }
    __syncthreads();
    sred[t] = sacc;
    __syncthreads();
    if (t < 128) sinv[t] = 1.0f / (1e-9f + sred[t] + sred[t + 128]);
    __syncthreads();
    #pragma unroll
    for (int ci = 0; ci < C / 8; ci++)
        #pragma unroll
        for (int jj = 0; jj < 4; jj++)
            xr[(b * C + c0 + ci) * NN + m0 + j0 + jj] = u[ci][jj] * sinv[j0 + jj];
}

// tp = wt @ (h - xr) + bt
template<int C>
__global__ void k_diffconv(const float* __restrict__ h, const float* __restrict__ xr,
                           const float* __restrict__ wt, const float* __restrict__ bt,
                           float* __restrict__ tp) {
    __shared__ float ws[C*C], bs[C];
    int t = threadIdx.x;
    for (int i = t; i < C*C; i += 256) ws[i] = wt[i];
    if (t < C) bs[t] = bt[t];
    __syncthreads();
    int b = blockIdx.y, n = blockIdx.x * 256 + t;
    float din[C];
    #pragma unroll
    for (int c = 0; c < C; c++)
        din[c] = h[(b * C + c) * NN + n] - xr[(b * C + c) * NN + n];
    for (int o = 0; o < C; o++) {
        float a = bs[o];
        #pragma unroll
        for (int c = 0; c < C; c++) a = fmaf(ws[o * C + c], din[c], a);
        tp[(b * C + o) * NN + n] = a;
    }
}

// out = h + relu(BN(tp))
template<int C>
__global__ void k_resid(const float* __restrict__ h, const float* __restrict__ tp,
                        const float* __restrict__ stat, const float* __restrict__ g,
                        const float* __restrict__ be, float* __restrict__ out) {
    int idx = blockIdx.x * 256 + threadIdx.x;
    int c = (idx >> 12) & (C - 1);
    float sc, sh;
    bn_coef(stat, g, be, c, sc, sh);
    float tv = fmaf(sc, tp[idx], sh);
    out[idx] = h[idx] + fmaxf(tv, 0.f);
}

// per-(b,c) max over N
__global__ void k_max(const float* __restrict__ d, float* __restrict__ gf) {
    int bc = blockIdx.x;
    const float* p = d + bc * NN;
    float m = -1e30f;
    for (int i = threadIdx.x; i < NN; i += 256) m = fmaxf(m, p[i]);
    __shared__ float sm_[8];
    for (int o = 16; o; o >>= 1) m = fmaxf(m, __shfl_down_sync(0xffffffffu, m, o));
    if ((threadIdx.x & 31) == 0) sm_[threadIdx.x >> 5] = m;
    __syncthreads();
    if (threadIdx.x == 0) {
        float M = sm_[0];
        #pragma unroll
        for (int i = 1; i < 8; i++) M = fmaxf(M, sm_[i]);
        gf[bc] = M;
    }
}

// y3 = w3 @ concat(h3, broadcast gf1) + b3
__global__ void k_concatconv(const float* __restrict__ h3, const float* __restrict__ gf1,
                             const float* __restrict__ w3, const float* __restrict__ b3,
                             float* __restrict__ y3) {
    __shared__ float ws[4096], K[64];
    int t = threadIdx.x, b = blockIdx.y;
    for (int i = t; i < 4096; i += 256) ws[i] = w3[i];
    __syncthreads();
    if (t < 64) {
        float a = b3[t];
        #pragma unroll
        for (int c = 0; c < 32; c++) a = fmaf(ws[t * 64 + 32 + c], gf1[b * 32 + c], a);
        K[t] = a;
    }
    __syncthreads();
    int n = blockIdx.x * 256 + t;
    float in[32];
    #pragma unroll
    for (int c = 0; c < 32; c++) in[c] = h3[(b * 32 + c) * NN + n];
    for (int o = 0; o < 64; o++) {
        float a = K[o];
        #pragma unroll
        for (int c = 0; c < 32; c++) a = fmaf(ws[o * 64 + c], in[c], a);
        y3[(b * 64 + o) * NN + n] = a;
    }
}

extern "C" void kernel_launch(void* const* d_in, const int* in_sizes, int n_in,
                              void* d_out, int out_size) {
    const float* x      = (const float*)d_in[0];
    const float* w1     = (const float*)d_in[1];
    const float* b1     = (const float*)d_in[2];
    const float* g1     = (const float*)d_in[3];
    const float* be1    = (const float*)d_in[4];
    const float* w2     = (const float*)d_in[5];
    const float* b2     = (const float*)d_in[6];
    const float* g2     = (const float*)d_in[7];
    const float* be2    = (const float*)d_in[8];
    const float* a1_wqk = (const float*)d_in[9];
    const float* a1_wv  = (const float*)d_in[10];
    const float* a1_bv  = (const float*)d_in[11];
    const float* a1_wt  = (const float*)d_in[12];
    const float* a1_bt  = (const float*)d_in[13];
    const float* a1_g   = (const float*)d_in[14];
    const float* a1_b   = (const float*)d_in[15];
    const float* w3     = (const float*)d_in[16];
    const float* b3     = (const float*)d_in[17];
    const float* g3     = (const float*)d_in[18];
    const float* be3    = (const float*)d_in[19];
    const float* a2_wqk = (const float*)d_in[20];
    const float* a2_wv  = (const float*)d_in[21];
    const float* a2_bv  = (const float*)d_in[22];
    const float* a2_wt  = (const float*)d_in[23];
    const float* a2_bt  = (const float*)d_in[24];
    const float* a2_g   = (const float*)d_in[25];
    const float* a2_b   = (const float*)d_in[26];

    float* S = nullptr;
    cudaGetSymbolAddress((void**)&S, SCR);
    float* y1  = S + 0 * BUF;   // also h4 (layer2)
    float* y2  = S + 1 * BUF;   // also y3
    float* h2  = S + 2 * BUF;
    float* qkb = S + 3 * BUF;
    float* vb  = S + 4 * BUF;
    float* xrb = S + 5 * BUF;
    float* tpb = S + 6 * BUF;
    float* h3  = S + 7 * BUF;
    float* Mr  = S + 8 * BUF;
    float* iL  = Mr + BB * NN;
    float* gf1 = iL + BB * NN;
    float* st  = gf1 + 256;     // 5 slots of 128

    float* outh  = (float*)d_out;
    float* outgf = outh + BB * 64 * NN;

    int smB32 = (32 * 128 + 32 * 32 * 2 + 32 * 132 + 256 + 128) * 4;
    int smB64 = (64 * 128 + 64 * 32 * 2 + 32 * 132 + 256 + 128) * 4;
    cudaFuncSetAttribute(k_attB<32>, cudaFuncAttributeMaxDynamicSharedMemorySize, smB32);
    cudaFuncSetAttribute(k_attB<64>, cudaFuncAttributeMaxDynamicSharedMemorySize, smB64);

    dim3 gN(NN / 256, BB), gA(NN / 128, BB);

    // stem
    k_conv1<<<gN, 256>>>(x, w1, b1, y1);
    k_stats<<<32, 256>>>(y1, 32, st + 0 * 128);
    k_bnconv32<<<gN, 256>>>(y1, st + 0 * 128, g1, be1, w2, b2, y2);
    k_stats<<<32, 256>>>(y2, 32, st + 1 * 128);
    // att1 (C=32)
    k_bnqkv<32><<<gN, 256>>>(y2, st + 1 * 128, g2, be2, a1_wqk, a1_wv, a1_bv, h2, qkb, vb);
    k_attA<32><<<gA, 256>>>(qkb, Mr, iL);
    k_attB<32><<<gA, 256, smB32>>>(qkb, vb, Mr, iL, xrb);
    k_diffconv<32><<<gN, 256>>>(h2, xrb, a1_wt, a1_bt, tpb);
    k_stats<<<32, 256>>>(tpb, 32, st + 2 * 128);
    k_resid<32><<<BB * 32 * NN / 256, 256>>>(h2, tpb, st + 2 * 128, a1_g, a1_b, h3);
    k_max<<<BB * 32, 256>>>(h3, gf1);
    // concat + conv3
    k_concatconv<<<gN, 256>>>(h3, gf1, w3, b3, y2);
    k_stats<<<64, 256>>>(y2, 64, st + 3 * 128);
    // att2 (C=64)
    k_bnqkv<64><<<gN, 256>>>(y2, st + 3 * 128, g3, be3, a2_wqk, a2_wv, a2_bv, y1, qkb, vb);
    k_attA<64><<<gA, 256>>>(qkb, Mr, iL);
    k_attB<64><<<gA, 256, smB64>>>(qkb, vb, Mr, iL, xrb);
    k_diffconv<64><<<gN, 256>>>(y1, xrb, a2_wt, a2_bt, tpb);
    k_stats<<<64, 256>>>(tpb, 64, st + 4 * 128);
    k_resid<64><<<BB * 64 * NN / 256, 256>>>(y1, tpb, st + 4 * 128, a2_g, a2_b, outh);
    k_max<<<BB * 64, 256>>>(outh, outgf);
}

// round 3
// speedup vs baseline: 1.0169x; 1.0169x over previous
#include <cuda_runtime.h>

#define NN 4096
#define BB 8
#define NBTOT (BB*NN)

typedef unsigned long long u64;

__device__ __forceinline__ u64 dup2(float x) {
    u64 r; asm("mov.b64 %0, {%1, %1};" : "=l"(r) : "f"(x)); return r;
}
__device__ __forceinline__ float2 unpk(u64 v) {
    float2 r; asm("mov.b64 {%0, %1}, %2;" : "=f"(r.x), "=f"(r.y) : "l"(v)); return r;
}
__device__ __forceinline__ void ffma2(u64& acc, u64 a, u64 b) {
    asm("fma.rn.f32x2 %0, %1, %2, %0;" : "+l"(acc) : "l"(a), "l"(b));
}

// ------------- scratch: one big device global (no allocations) -------------
#define BUF 2097152  // BB*64*NN
__device__ float SCR[8*BUF + 2*BB*NN + 256 + 5*128 + 1024];

// stats slot layout: stat[c] = sum, stat[64+c] = sumsq
__device__ __forceinline__ void bn_coef(const float* __restrict__ stat,
                                        const float* __restrict__ g,
                                        const float* __restrict__ be,
                                        int c, float& sc, float& sh) {
    const float inv = 1.0f / (float)NBTOT;
    float mean = stat[c] * inv;
    float var  = stat[64 + c] * inv - mean * mean;
    float r = rsqrtf(var + 1e-5f);
    sc = g[c] * r;
    sh = be[c] - sc * mean;
}

// stage 1: per-(c,b) sum & sumsq; grid (C, BB)
__global__ void k_stats1(const float* __restrict__ d, int C, float* __restrict__ st2) {
    int c = blockIdx.x, b = blockIdx.y;
    const float* p = d + (b * C + c) * NN;
    float s = 0.f, sq = 0.f;
    for (int i = threadIdx.x; i < NN; i += 256) {
        float v = p[i];
        s += v; sq += v * v;
    }
    __shared__ float shs[8], shq[8];
    for (int o = 16; o; o >>= 1) {
        s  += __shfl_down_sync(0xffffffffu, s, o);
        sq += __shfl_down_sync(0xffffffffu, sq, o);
    }
    if ((threadIdx.x & 31) == 0) { shs[threadIdx.x >> 5] = s; shq[threadIdx.x >> 5] = sq; }
    __syncthreads();
    if (threadIdx.x == 0) {
        float S = 0.f, Q = 0.f;
        #pragma unroll
        for (int i = 0; i < 8; i++) { S += shs[i]; Q += shq[i]; }
        st2[b * 128 + c] = S; st2[b * 128 + 64 + c] = Q;
    }
}
// stage 2: reduce over b in fixed order; 1 block, 64 threads
__global__ void k_stats2(const float* __restrict__ st2, int C, float* __restrict__ stat) {
    int t = threadIdx.x;
    if (t < C) {
        float S = 0.f, Q = 0.f;
        #pragma unroll
        for (int b = 0; b < BB; b++) { S += st2[b * 128 + t]; Q += st2[b * 128 + 64 + t]; }
        stat[t] = S; stat[64 + t] = Q;
    }
}

// stem conv: x[8,6,N] -> y[8,32,N]
__global__ void k_conv1(const float* __restrict__ x, const float* __restrict__ w,
                        const float* __restrict__ bias, float* __restrict__ y) {
    __shared__ float ws[192], bs[32];
    int t = threadIdx.x;
    if (t < 192) ws[t] = w[t];
    if (t < 32)  bs[t] = bias[t];
    __syncthreads();
    int b = blockIdx.y, n = blockIdx.x * 256 + t;
    float in[6];
    #pragma unroll
    for (int c = 0; c < 6; c++) in[c] = x[(b * 6 + c) * NN + n];
    #pragma unroll
    for (int o = 0; o < 32; o++) {
        float a = bs[o];
        #pragma unroll
        for (int c = 0; c < 6; c++) a = fmaf(ws[o * 6 + c], in[c], a);
        y[(b * 32 + o) * NN + n] = a;
    }
}

// BN(stats)+relu then 32x32 conv
__global__ void k_bnconv32(const float* __restrict__ yin, const float* __restrict__ stat,
                           const float* __restrict__ g, const float* __restrict__ be,
                           const float* __restrict__ w, const float* __restrict__ bias,
                           float* __restrict__ yout) {
    __shared__ float ws[1024], bs[32], sc[32], sh[32];
    int t = threadIdx.x;
    for (int i = t; i < 1024; i += 256) ws[i] = w[i];
    if (t < 32) { bs[t] = bias[t]; bn_coef(stat, g, be, t, sc[t], sh[t]); }
    __syncthreads();
    int b = blockIdx.y, n = blockIdx.x * 256 + t;
    float in[32];
    #pragma unroll
    for (int c = 0; c < 32; c++)
        in[c] = fmaxf(fmaf(sc[c], yin[(b * 32 + c) * NN + n], sh[c]), 0.f);
    for (int o = 0; o < 32; o++) {
        float a = bs[o];
        #pragma unroll
        for (int c = 0; c < 32; c++) a = fmaf(ws[o * 32 + c], in[c], a);
        yout[(b * 32 + o) * NN + n] = a;
    }
}

// BN+relu -> h; qk = wqk@h; v = wv@h + bv
template<int C>
__global__ void k_bnqkv(const float* __restrict__ yin, const float* __restrict__ stat,
                        const float* __restrict__ g, const float* __restrict__ be,
                        const float* __restrict__ wqk, const float* __restrict__ wv,
                        const float* __restrict__ bv,
                        float* __restrict__ h, float* __restrict__ qk, float* __restrict__ v) {
    __shared__ float wq_s[C*C], wv_s[C*C], bvs[C], sc[C], sh[C];
    int t = threadIdx.x;
    for (int i = t; i < C*C; i += 256) { wq_s[i] = wqk[i]; wv_s[i] = wv[i]; }
    if (t < C) { bvs[t] = bv[t]; bn_coef(stat, g, be, t, sc[t], sh[t]); }
    __syncthreads();
    int b = blockIdx.y, n = blockIdx.x * 256 + t;
    float in[C];
    #pragma unroll
    for (int c = 0; c < C; c++) {
        float val = fmaxf(fmaf(sc[c], yin[(b * C + c) * NN + n], sh[c]), 0.f);
        in[c] = val;
        h[(b * C + c) * NN + n] = val;
    }
    for (int o = 0; o < C; o++) {
        float aq = 0.f, av = bvs[o];
        #pragma unroll
        for (int c = 0; c < C; c++) {
            aq = fmaf(wq_s[o * C + c], in[c], aq);
            av = fmaf(wv_s[o * C + c], in[c], av);
        }
        qk[(b * C + o) * NN + n] = aq;
        v [(b * C + o) * NN + n] = av;
    }
}

// ---------------- attention pass A: per-row max + sumexp ----------------
// grid (NN/128, BB), 256 thr. A tile (n-block) persistent; B tiles streamed.
// FFMA2 inner loop, 8x8 microtile per thread (acc packed over m-dim).
template<int C>
__global__ void k_attA(const float* __restrict__ qk, float* __restrict__ Mr,
                       float* __restrict__ iL) {
    extern __shared__ float dsm[];
    float* As = dsm;            // C*128
    float* Bs = dsm + C * 128;  // C*128
    __shared__ float RM[128][17], RL[128][17];
    const int b = blockIdx.y, n0 = blockIdx.x * 128, t = threadIdx.x;
    const int rowg = t >> 4, colg = t & 15;

    for (int idx = t; idx < C * 128; idx += 256) {
        int k = idx >> 7, i = idx & 127;
        As[idx] = qk[(b * C + k) * NN + n0 + i];
    }

    float Mloc[8], Lloc[8];
    #pragma unroll
    for (int i = 0; i < 8; i++) { Mloc[i] = -1e30f; Lloc[i] = 0.f; }

    for (int mt = 0; mt < NN / 128; mt++) {
        const int m0 = mt * 128;
        __syncthreads();
        for (int idx = t; idx < C * 128; idx += 256) {
            int k = idx >> 7, i = idx & 127;
            Bs[idx] = qk[(b * C + k) * NN + m0 + i];
        }
        __syncthreads();
        u64 acc[8][4];
        #pragma unroll
        for (int i = 0; i < 8; i++)
            #pragma unroll
            for (int j = 0; j < 4; j++) acc[i][j] = 0ULL;
        #pragma unroll 4
        for (int k = 0; k < C; k++) {
            float4 a0 = *(float4*)&As[k * 128 + rowg * 8];
            float4 a1 = *(float4*)&As[k * 128 + rowg * 8 + 4];
            ulonglong2 b0 = *(ulonglong2*)&Bs[k * 128 + colg * 8];
            ulonglong2 b1 = *(ulonglong2*)&Bs[k * 128 + colg * 8 + 4];
            float a[8] = {a0.x, a0.y, a0.z, a0.w, a1.x, a1.y, a1.z, a1.w};
            u64 bp[4] = {b0.x, b0.y, b1.x, b1.y};
            #pragma unroll
            for (int i = 0; i < 8; i++) {
                u64 ad = dup2(a[i]);
                #pragma unroll
                for (int j = 0; j < 4; j++) ffma2(acc[i][j], ad, bp[j]);
            }
        }
        // online softmax update (rows = n-dim, cols = m-dim)
        #pragma unroll
        for (int i = 0; i < 8; i++) {
            float s[8];
            #pragma unroll
            for (int j = 0; j < 4; j++) {
                float2 p = unpk(acc[i][j]);
                s[2 * j] = p.x; s[2 * j + 1] = p.y;
            }
            float tmax = s[0];
            #pragma unroll
            for (int j = 1; j < 8; j++) tmax = fmaxf(tmax, s[j]);
            float Mn = fmaxf(Mloc[i], tmax);
            float l = Lloc[i] * __expf(Mloc[i] - Mn);
            #pragma unroll
            for (int j = 0; j < 8; j++) l += __expf(s[j] - Mn);
            Mloc[i] = Mn; Lloc[i] = l;
        }
    }
    __syncthreads();
    #pragma unroll
    for (int i = 0; i < 8; i++) {
        RM[rowg * 8 + i][colg] = Mloc[i];
        RL[rowg * 8 + i][colg] = Lloc[i];
    }
    __syncthreads();
    if (t < 128) {
        float M = -1e30f, L = 0.f;
        #pragma unroll
        for (int p = 0; p < 16; p++) {
            float m2 = RM[t][p], l2 = RL[t][p];
            float Mn = fmaxf(M, m2);
            L = L * __expf(M - Mn) + l2 * __expf(m2 - Mn);
            M = Mn;
        }
        Mr[b * NN + n0 + t] = M;
        iL[b * NN + n0 + t] = 1.0f / L;
    }
}

// ---------------- attention pass B: column sums + V*attn + renorm ----------------
// grid (NN/128 col-tiles, BB), 256 thr, dynamic smem. FFMA2 everywhere.
template<int C>
__global__ void k_attB(const float* __restrict__ qk, const float* __restrict__ v,
                       const float* __restrict__ Mr, const float* __restrict__ iLp,
                       float* __restrict__ xr) {
    constexpr int VS = C + 2;      // padded V-transpose stride
    constexpr int NP = C / 16;     // channel pairs per thread
    extern __shared__ float dsm[];
    float* Qm   = dsm;               // C*128
    float* Qn   = Qm + C * 128;      // C*32
    float* VsT  = Qn + C * 32;       // 32*VS   (VsT[i*VS + c])
    float* Es   = VsT + 32 * VS;     // 32*132
    float* sred = Es + 32 * 132;     // 256
    float* sinv = sred + 256;        // 128
    __shared__ float Ms[32], Ls[32];

    const int b = blockIdx.y, m0 = blockIdx.x * 128, t = threadIdx.x;
    for (int idx = t; idx < C * 128; idx += 256) {
        int k = idx >> 7, j = idx & 127;
        Qm[k * 128 + j] = qk[(b * C + k) * NN + m0 + j];
    }
    const int i0 = (t >> 5) * 4;       // S rows (n-dim within tile)
    const int j0 = (t & 31) * 4;       // S / u cols (m-dim)
    const int c0 = (t >> 5) * (C / 8); // u channel base
    const int jjs = t & 127, hf = t >> 7;

    u64 u2[NP][4];
    #pragma unroll
    for (int ci = 0; ci < NP; ci++)
        #pragma unroll
        for (int j = 0; j < 4; j++) u2[ci][j] = 0ULL;
    float sacc = 0.f;

    for (int nt = 0; nt < NN / 32; nt++) {
        const int n0 = nt * 32;
        __syncthreads();
        for (int idx = t; idx < C * 32; idx += 256) {
            int k = idx >> 5, i = idx & 31;
            Qn[idx] = qk[(b * C + k) * NN + n0 + i];
            VsT[i * VS + k] = v[(b * C + k) * NN + n0 + i];
        }
        if (t < 32) { Ms[t] = Mr[b * NN + n0 + t]; Ls[t] = iLp[b * NN + n0 + t]; }
        __syncthreads();

        u64 s2[4][2];
        #pragma unroll
        for (int i = 0; i < 4; i++) { s2[i][0] = 0ULL; s2[i][1] = 0ULL; }
        #pragma unroll 8
        for (int k = 0; k < C; k++) {
            float4 av = *(float4*)&Qn[k * 32 + i0];
            ulonglong2 bv = *(ulonglong2*)&Qm[k * 128 + j0];
            float a[4] = {av.x, av.y, av.z, av.w};
            #pragma unroll
            for (int i = 0; i < 4; i++) {
                u64 ad = dup2(a[i]);
                ffma2(s2[i][0], ad, bv.x);
                ffma2(s2[i][1], ad, bv.y);
            }
        }
        #pragma unroll
        for (int ii = 0; ii < 4; ii++) {
            float m = Ms[i0 + ii], il = Ls[i0 + ii];
            float2 p0 = unpk(s2[ii][0]), p1 = unpk(s2[ii][1]);
            float4 ev;
            ev.x = __expf(p0.x - m) * il;
            ev.y = __expf(p0.y - m) * il;
            ev.z = __expf(p1.x - m) * il;
            ev.w = __expf(p1.y - m) * il;
            *(float4*)&Es[(i0 + ii) * 132 + j0] = ev;
        }
        __syncthreads();
        #pragma unroll
        for (int i = 0; i < 16; i++) sacc += Es[(hf * 16 + i) * 132 + jjs];
        #pragma unroll 8
        for (int i = 0; i < 32; i++) {
            float4 ev4 = *(float4*)&Es[i * 132 + j0];
            u64 ed[4] = {dup2(ev4.x), dup2(ev4.y), dup2(ev4.z), dup2(ev4.w)};
            #pragma unroll
            for (int ci = 0; ci < NP; ci++) {
                u64 vp = *(u64*)&VsT[i * VS + c0 + 2 * ci];
                #pragma unroll
                for (int j = 0; j < 4; j++) ffma2(u2[ci][j], vp, ed[j]);
            }
        }
    }
    __syncthreads();
    sred[t] = sacc;
    __syncthreads();
    if (t < 128) sinv[t] = 1.0f / (1e-9f + sred[t] + sred[t + 128]);
    __syncthreads();
    #pragma unroll
    for (int ci = 0; ci < NP; ci++)
        #pragma unroll
        for (int j = 0; j < 4; j++) {
            float2 uu = unpk(u2[ci][j]);
            float si = sinv[j0 + j];
            int col = m0 + j0 + j;
            xr[(b * C + c0 + 2 * ci)     * NN + col] = uu.x * si;
            xr[(b * C + c0 + 2 * ci + 1) * NN + col] = uu.y * si;
        }
}

// tp = wt @ (h - xr) + bt
template<int C>
__global__ void k_diffconv(const float* __restrict__ h, const float* __restrict__ xr,
                           const float* __restrict__ wt, const float* __restrict__ bt,
                           float* __restrict__ tp) {
    __shared__ float ws[C*C], bs[C];
    int t = threadIdx.x;
    for (int i = t; i < C*C; i += 256) ws[i] = wt[i];
    if (t < C) bs[t] = bt[t];
    __syncthreads();
    int b = blockIdx.y, n = blockIdx.x * 256 + t;
    float din[C];
    #pragma unroll
    for (int c = 0; c < C; c++)
        din[c] = h[(b * C + c) * NN + n] - xr[(b * C + c) * NN + n];
    for (int o = 0; o < C; o++) {
        float a = bs[o];
        #pragma unroll
        for (int c = 0; c < C; c++) a = fmaf(ws[o * C + c], din[c], a);
        tp[(b * C + o) * NN + n] = a;
    }
}

// out = h + relu(BN(tp))
template<int C>
__global__ void k_resid(const float* __restrict__ h, const float* __restrict__ tp,
                        const float* __restrict__ stat, const float* __restrict__ g,
                        const float* __restrict__ be, float* __restrict__ out) {
    int idx = blockIdx.x * 256 + threadIdx.x;
    int c = (idx >> 12) & (C - 1);
    float sc, sh;
    bn_coef(stat, g, be, c, sc, sh);
    float tv = fmaf(sc, tp[idx], sh);
    out[idx] = h[idx] + fmaxf(tv, 0.f);
}

// per-(b,c) max over N
__global__ void k_max(const float* __restrict__ d, float* __restrict__ gf) {
    int bc = blockIdx.x;
    const float* p = d + bc * NN;
    float m = -1e30f;
    for (int i = threadIdx.x; i < NN; i += 256) m = fmaxf(m, p[i]);
    __shared__ float sm_[8];
    for (int o = 16; o; o >>= 1) m = fmaxf(m, __shfl_down_sync(0xffffffffu, m, o));
    if ((threadIdx.x & 31) == 0) sm_[threadIdx.x >> 5] = m;
    __syncthreads();
    if (threadIdx.x == 0) {
        float M = sm_[0];
        #pragma unroll
        for (int i = 1; i < 8; i++) M = fmaxf(M, sm_[i]);
        gf[bc] = M;
    }
}

// y3 = w3 @ concat(h3, broadcast gf1) + b3
__global__ void k_concatconv(const float* __restrict__ h3, const float* __restrict__ gf1,
                             const float* __restrict__ w3, const float* __restrict__ b3,
                             float* __restrict__ y3) {
    __shared__ float ws[4096], K[64];
    int t = threadIdx.x, b = blockIdx.y;
    for (int i = t; i < 4096; i += 256) ws[i] = w3[i];
    __syncthreads();
    if (t < 64) {
        float a = b3[t];
        #pragma unroll
        for (int c = 0; c < 32; c++) a = fmaf(ws[t * 64 + 32 + c], gf1[b * 32 + c], a);
        K[t] = a;
    }
    __syncthreads();
    int n = blockIdx.x * 256 + t;
    float in[32];
    #pragma unroll
    for (int c = 0; c < 32; c++) in[c] = h3[(b * 32 + c) * NN + n];
    for (int o = 0; o < 64; o++) {
        float a = K[o];
        #pragma unroll
        for (int c = 0; c < 32; c++) a = fmaf(ws[o * 64 + c], in[c], a);
        y3[(b * 64 + o) * NN + n] = a;
    }
}

extern "C" void kernel_launch(void* const* d_in, const int* in_sizes, int n_in,
                              void* d_out, int out_size) {
    const float* x      = (const float*)d_in[0];
    const float* w1     = (const float*)d_in[1];
    const float* b1     = (const float*)d_in[2];
    const float* g1     = (const float*)d_in[3];
    const float* be1    = (const float*)d_in[4];
    const float* w2     = (const float*)d_in[5];
    const float* b2     = (const float*)d_in[6];
    const float* g2     = (const float*)d_in[7];
    const float* be2    = (const float*)d_in[8];
    const float* a1_wqk = (const float*)d_in[9];
    const float* a1_wv  = (const float*)d_in[10];
    const float* a1_bv  = (const float*)d_in[11];
    const float* a1_wt  = (const float*)d_in[12];
    const float* a1_bt  = (const float*)d_in[13];
    const float* a1_g   = (const float*)d_in[14];
    const float* a1_b   = (const float*)d_in[15];
    const float* w3     = (const float*)d_in[16];
    const float* b3     = (const float*)d_in[17];
    const float* g3     = (const float*)d_in[18];
    const float* be3    = (const float*)d_in[19];
    const float* a2_wqk = (const float*)d_in[20];
    const float* a2_wv  = (const float*)d_in[21];
    const float* a2_bv  = (const float*)d_in[22];
    const float* a2_wt  = (const float*)d_in[23];
    const float* a2_bt  = (const float*)d_in[24];
    const float* a2_g   = (const float*)d_in[25];
    const float* a2_b   = (const float*)d_in[26];

    float* S = nullptr;
    cudaGetSymbolAddress((void**)&S, SCR);
    float* y1  = S + 0 * BUF;   // also h4 (layer2)
    float* y2  = S + 1 * BUF;   // also y3
    float* h2  = S + 2 * BUF;
    float* qkb = S + 3 * BUF;
    float* vb  = S + 4 * BUF;
    float* xrb = S + 5 * BUF;
    float* tpb = S + 6 * BUF;
    float* h3  = S + 7 * BUF;
    float* Mr  = S + 8 * BUF;
    float* iL  = Mr + BB * NN;
    float* gf1 = iL + BB * NN;
    float* st  = gf1 + 256;     // 5 slots of 128
    float* st2 = st + 5 * 128;  // 1024 partials

    float* outh  = (float*)d_out;
    float* outgf = outh + BB * 64 * NN;

    int smA32 = 32 * 128 * 2 * 4;
    int smA64 = 64 * 128 * 2 * 4;
    int smB32 = (32 * 128 + 32 * 32 + 32 * (32 + 2) + 32 * 132 + 256 + 128) * 4;
    int smB64 = (64 * 128 + 64 * 32 + 32 * (64 + 2) + 32 * 132 + 256 + 128) * 4;
    cudaFuncSetAttribute(k_attA<32>, cudaFuncAttributeMaxDynamicSharedMemorySize, smA32);
    cudaFuncSetAttribute(k_attA<64>, cudaFuncAttributeMaxDynamicSharedMemorySize, smA64);
    cudaFuncSetAttribute(k_attB<32>, cudaFuncAttributeMaxDynamicSharedMemorySize, smB32);
    cudaFuncSetAttribute(k_attB<64>, cudaFuncAttributeMaxDynamicSharedMemorySize, smB64);

    dim3 gN(NN / 256, BB), gA(NN / 128, BB);

    // stem
    k_conv1<<<gN, 256>>>(x, w1, b1, y1);
    k_stats1<<<dim3(32, BB), 256>>>(y1, 32, st2);
    k_stats2<<<1, 64>>>(st2, 32, st + 0 * 128);
    k_bnconv32<<<gN, 256>>>(y1, st + 0 * 128, g1, be1, w2, b2, y2);
    k_stats1<<<dim3(32, BB), 256>>>(y2, 32, st2);
    k_stats2<<<1, 64>>>(st2, 32, st + 1 * 128);
    // att1 (C=32)
    k_bnqkv<32><<<gN, 256>>>(y2, st + 1 * 128, g2, be2, a1_wqk, a1_wv, a1_bv, h2, qkb, vb);
    k_attA<32><<<gA, 256, smA32>>>(qkb, Mr, iL);
    k_attB<32><<<gA, 256, smB32>>>(qkb, vb, Mr, iL, xrb);
    k_diffconv<32><<<gN, 256>>>(h2, xrb, a1_wt, a1_bt, tpb);
    k_stats1<<<dim3(32, BB), 256>>>(tpb, 32, st2);
    k_stats2<<<1, 64>>>(st2, 32, st + 2 * 128);
    k_resid<32><<<BB * 32 * NN / 256, 256>>>(h2, tpb, st + 2 * 128, a1_g, a1_b, h3);
    k_max<<<BB * 32, 256>>>(h3, gf1);
    // concat + conv3
    k_concatconv<<<gN, 256>>>(h3, gf1, w3, b3, y2);
    k_stats1<<<dim3(64, BB), 256>>>(y2, 64, st2);
    k_stats2<<<1, 64>>>(st2, 64, st + 3 * 128);
    // att2 (C=64)
    k_bnqkv<64><<<gN, 256>>>(y2, st + 3 * 128, g3, be3, a2_wqk, a2_wv, a2_bv, y1, qkb, vb);
    k_attA<64><<<gA, 256, smA64>>>(qkb, Mr, iL);
    k_attB<64><<<gA, 256, smB64>>>(qkb, vb, Mr, iL, xrb);
    k_diffconv<64><<<gN, 256>>>(y1, xrb, a2_wt, a2_bt, tpb);
    k_stats1<<<dim3(64, BB), 256>>>(tpb, 64, st2);
    k_stats2<<<1, 64>>>(st2, 64, st + 4 * 128);
    k_resid<64><<<BB * 64 * NN / 256, 256>>>(y1, tpb, st + 4 * 128, a2_g, a2_b, outh);
    k_max<<<BB * 64, 256>>>(outh, outgf);
}